// round 17
// baseline (speedup 1.0000x reference)
#include <cuda_runtime.h>

// Problem constants
#define B_    128
#define T_    1024
#define H_    512
#define I_    64
#define KA    576              // augmented K = H + I
#define NCTA  128              // 16 clusters x 8 CTAs
#define NTHR  512
#define NWARP 16
#define CLU   8                // CTAs per cluster (h-split)
#define HT    64               // h-rows per CTA
#define BT    8                // b-cols per CTA (= per cluster slice)
#define KW    36               // k per warp (16 x 36 = 576)
#define C1    0.9f
#define C2    0.1f

// smem floats: wtile[KA][64] + stile[KA][8] + hs[64][9] + red[16][32][16]
#define WT_F  (KA * 64)                // 36864 (147.5 KB) one-time W slice
#define ST_F  (KA * BT)                // 4608  (18.4 KB) per-step S ++ x
#define HS_F  (HT * 9)                 // 576   padded h tile
#define RED_F (NWARP * 32 * 16)        // 8192  K-split partials
#define SMEM_FLOATS (WT_F + ST_F + HS_F + RED_F)
#define SMEM_BYTES  (SMEM_FLOATS * 4)  // ~201 KB -> 1 CTA/SM

// ---- global scratch (__device__ globals: allocation-free rule) ----
__device__ float g_S[2][H_ * B_];      // double-buffered sigmoid(h)

__device__ __forceinline__ void fma2(unsigned long long &acc,
                                     unsigned long long a,
                                     unsigned long long b) {
    asm("fma.rn.f32x2 %0, %1, %2, %0;" : "+l"(acc) : "l"(a), "l"(b));
}

__device__ __forceinline__ unsigned long long dup2(float v) {
    unsigned long long r;
    asm("mov.b64 %0, {%1, %1};" : "=l"(r) : "f"(v));
    return r;
}

__device__ __forceinline__ float sigmoidf_(float x) {
    return 1.0f / (1.0f + __expf(-x));
}

// Cluster-wide barrier; cross-CTA S data travels via L2 (.cg), ordered by the
// threadfence before arrive. HW co-schedules cluster CTAs: no hang risk.
__device__ __forceinline__ void cluster_sync_l2() {
    __threadfence();                   // S/out stores visible at L2
    asm volatile("barrier.cluster.arrive.aligned;" ::: "memory");
    asm volatile("barrier.cluster.wait.aligned;"   ::: "memory");
}

__global__ void __launch_bounds__(NTHR, 1) __cluster_dims__(CLU, 1, 1)
rnn_cluster_kernel(const float* __restrict__ x,      // [B,T,I]
                   const float* __restrict__ W_in,   // [H,I]
                   const float* __restrict__ W_h,    // [H,H]
                   const float* __restrict__ sigma,  // [H,T,B]
                   const float* __restrict__ h0,     // [H,B]
                   float* __restrict__ out)          // [B,T,H] ++ [H,B]
{
    extern __shared__ float sm[];
    float* wtile = sm;                     // [KA][64]  W_aug slice (one-time)
    float* stile = sm + WT_F;              // [KA][8]   staged S ++ x rows
    float* hs    = sm + WT_F + ST_F;       // [64][9]   h tile (padded)
    float* red   = sm + WT_F + ST_F + HS_F;// [16w][32lane][16]

    const int tid  = threadIdx.x;
    const int warp = tid >> 5;
    const int lane = tid & 31;

    unsigned int rank;                     // CTA rank within cluster (h-split)
    asm("mov.u32 %0, %%cluster_ctarank;" : "=r"(rank));
    const int h0r = rank * HT;             // this CTA's 64 h-rows
    const int b0  = (blockIdx.x >> 3) * BT;// cluster's 8 b-columns

    // ---- one-time: wtile[k][h] = W_aug[h0r+h][k]
    // thread -> h = tid>>3 (0..63), k4 = (tid&7) + 8*it (0..143)
    {
        const int h  = tid >> 3;
        const int kb = tid & 7;
        #pragma unroll
        for (int it = 0; it < 18; ++it) {
            int k4 = kb + 8 * it;
            float4 w4 = (k4 < 128)
                ? *(const float4*)(W_h  + (size_t)(h0r + h) * H_ + 4 * k4)
                : *(const float4*)(W_in + (size_t)(h0r + h) * I_ + 4 * k4 - 512);
            wtile[(4 * k4 + 0) * 64 + h] = w4.x;
            wtile[(4 * k4 + 1) * 64 + h] = w4.y;
            wtile[(4 * k4 + 2) * 64 + h] = w4.z;
            wtile[(4 * k4 + 3) * 64 + h] = w4.w;
        }
    }

    // ---- init h tile + publish sigmoid(h0) into buffer 0
    const int uH = tid >> 3;               // update-map h (0..63)
    const int uB = tid & 7;                // update-map b (0..7)
    {
        float h = h0[(size_t)(h0r + uH) * B_ + b0 + uB];
        hs[uH * 9 + uB] = h;
        __stcg(&g_S[0][(size_t)(h0r + uH) * B_ + b0 + uB], sigmoidf_(h));
    }
    __syncthreads();
    cluster_sync_l2();

    const int hgrp = lane >> 1;            // 0..15 -> h base 4*hgrp
    const int bgrp = lane & 1;             // 0..1  -> b base 4*bgrp
    const int rlp  = ((uH >> 2) << 1) | (uB >> 2);   // GEMM lane owning cell
    const int roff = (uH & 3) * 4 + (uB & 3);        // float offset in block

    int p = 0;
    for (int t = 0; t < T_; ++t) {
        // sigma prefetch (consumed in update; hides DRAM latency under GEMM)
        float sgv = __ldg(sigma + ((size_t)(h0r + uH) * T_ + t) * B_ + b0 + uB);

        // ---- stage stile rows 0..511 from g_S[p] (L2, .cg); 2 float4/thread
        {
            int r = tid;                   // one row per thread
            const float* sp = g_S[p] + (size_t)r * B_ + b0;
            float4 v0 = __ldcg((const float4*)(sp + 0));
            float4 v1 = __ldcg((const float4*)(sp + 4));
            *(float4*)(stile + r * BT + 0) = v0;
            *(float4*)(stile + r * BT + 4) = v1;
        }
        // ---- stage x rows 512..575 (transposed): i = tid&63, b = tid>>6
        {
            int i = tid & 63, b = tid >> 6;
            float xv = __ldg(x + ((size_t)(b0 + b) * T_ + t) * I_ + i);
            stile[(H_ + i) * BT + b] = xv;
        }
        __syncthreads();

        // ---- GEMM: lane = 4h x 4b; 1 w-LDS.128 + 1 s-LDS.128 + 8 FFMA2 / k
        unsigned long long acc[4][2];
        #pragma unroll
        for (int i = 0; i < 4; ++i) { acc[i][0] = 0ull; acc[i][1] = 0ull; }
        {
            const float* wp = wtile + (KW * warp) * 64 + 4 * hgrp;
            const float* sp = stile + (KW * warp) * BT + 4 * bgrp;
            #pragma unroll
            for (int j = 0; j < KW; ++j) {
                float4 w4 = *(const float4*)(wp + j * 64);
                ulonglong2 s2 = *(const ulonglong2*)(sp + j * BT);
                unsigned long long wd0 = dup2(w4.x), wd1 = dup2(w4.y);
                unsigned long long wd2 = dup2(w4.z), wd3 = dup2(w4.w);
                fma2(acc[0][0], wd0, s2.x); fma2(acc[0][1], wd0, s2.y);
                fma2(acc[1][0], wd1, s2.x); fma2(acc[1][1], wd1, s2.y);
                fma2(acc[2][0], wd2, s2.x); fma2(acc[2][1], wd2, s2.y);
                fma2(acc[3][0], wd3, s2.x); fma2(acc[3][1], wd3, s2.y);
            }
        }

        // ---- store K-split partials: 64B block per (warp, lane)
        {
            ulonglong2* blk = (ulonglong2*)(red + (warp * 32 + lane) * 16);
            blk[0] = make_ulonglong2(acc[0][0], acc[0][1]);
            blk[1] = make_ulonglong2(acc[1][0], acc[1][1]);
            blk[2] = make_ulonglong2(acc[2][0], acc[2][1]);
            blk[3] = make_ulonglong2(acc[3][0], acc[3][1]);
        }
        __syncthreads();

        // ---- reduce 16 partials + leaky update + S publish
        {
            float s = 0.f;
            #pragma unroll
            for (int w = 0; w < NWARP; ++w)
                s += red[(w * 32 + rlp) * 16 + roff];
            float hn = C1 * hs[uH * 9 + uB] + C2 * (s + sgv);
            hs[uH * 9 + uB] = hn;
            __stcg(&g_S[1 - p][(size_t)(h0r + uH) * B_ + b0 + uB], sigmoidf_(hn));
        }
        __syncthreads();

        // ---- coalesced out tile [B,T,H]: 64 consecutive h per b-group
        {
            int ob = tid >> 6, oh = tid & 63;
            out[((size_t)(b0 + ob) * T_ + t) * H_ + h0r + oh] = hs[oh * 9 + ob];
        }

        cluster_sync_l2();                 // only this cluster's 8 CTAs
        p ^= 1;
    }

    // ---- h_last [H,B] appended after out [B,T,H]
    out[(size_t)B_ * T_ * H_ + (size_t)(h0r + uH) * B_ + b0 + uB] = hs[uH * 9 + uB];
}

extern "C" void kernel_launch(void* const* d_in, const int* in_sizes, int n_in,
                              void* d_out, int out_size) {
    const float* x    = (const float*)d_in[0];
    const float* W_in = (const float*)d_in[1];
    const float* W_h  = (const float*)d_in[2];
    const float* sg   = (const float*)d_in[3];
    const float* h0   = (const float*)d_in[4];
    float* out = (float*)d_out;

    static int smem_set = 0;
    if (!smem_set) {
        cudaFuncSetAttribute(rnn_cluster_kernel,
                             cudaFuncAttributeMaxDynamicSharedMemorySize, SMEM_BYTES);
        smem_set = 1;
    }

    rnn_cluster_kernel<<<NCTA, NTHR, SMEM_BYTES>>>(x, W_in, W_h, sg, h0, out);
}